// round 3
// baseline (speedup 1.0000x reference)
#include <cuda_runtime.h>

#define LEN_HIS 20
#define D_IN    36
#define HID     64
#define G3      192   // 3*HID
#define DIM_C   4
#define MAXN    32768

// scratch (no allocations allowed)
__device__ float g_GI[MAXN * G3];     // precomputed input gates: emb @ W_ih^T + b_ih
__device__ int   g_start[MAXN];       // window start per timestep

__device__ __forceinline__ float sigmoidf_(float x) {
    return __fdividef(1.0f, 1.0f + __expf(-x));
}
__device__ __forceinline__ float tanhf_(float x) {
    // tanh(x) = 2/(1+e^{-2x}) - 1 ; stable at both tails, ~2^-21 rel err
    return __fdividef(2.0f, 1.0f + __expf(-2.0f * x)) - 1.0f;
}

// ---------------------------------------------------------------------------
// Kernel A: GI[t][j] = b_ih[j] + sum_k emb[t][k] * W_ih[j][k]; also window starts
// 192 threads, each block handles 64 timesteps. W_ih staged transposed in smem.
// ---------------------------------------------------------------------------
__global__ void __launch_bounds__(192) precompute_kernel(
    const float* __restrict__ emb,
    const float* __restrict__ W_ih,
    const float* __restrict__ b_ih,
    const int*  __restrict__ dones,
    int n)
{
    __shared__ float sW[D_IN * G3];        // [k][j] transposed -> conflict-free
    __shared__ float sX[64 * D_IN];
    const int tid = threadIdx.x;           // 0..191
    const int t0  = blockIdx.x * 64;

    for (int idx = tid; idx < G3 * D_IN; idx += 192) {
        int j = idx / D_IN, k = idx % D_IN;
        sW[k * G3 + j] = W_ih[idx];
    }
    const int nt = min(64, n - t0);
    for (int idx = tid; idx < nt * D_IN; idx += 192)
        sX[idx] = emb[t0 * D_IN + idx];
    __syncthreads();

    const float bj = b_ih[tid];
    for (int tt = 0; tt < nt; ++tt) {
        float a0 = bj, a1 = 0.f, a2 = 0.f, a3 = 0.f;
        const float* x = &sX[tt * D_IN];
        #pragma unroll
        for (int k = 0; k < 36; k += 4) {
            a0 = fmaf(sW[(k + 0) * G3 + tid], x[k + 0], a0);
            a1 = fmaf(sW[(k + 1) * G3 + tid], x[k + 1], a1);
            a2 = fmaf(sW[(k + 2) * G3 + tid], x[k + 2], a2);
            a3 = fmaf(sW[(k + 3) * G3 + tid], x[k + 3], a3);
        }
        g_GI[(t0 + tt) * G3 + tid] = (a0 + a1) + (a2 + a3);
    }

    // window start: last done in [max(0,t-19), t-1] -> start = d+1
    if (tid < 64) {
        int t = t0 + tid;
        if (t < n) {
            int s = t - (LEN_HIS - 1);
            if (s < 0) s = 0;
            int st = s;
            for (int k = s; k < t; ++k)
                if (dones[k] != 0) st = k + 1;
            g_start[t] = st;
        }
    }
}

// ---------------------------------------------------------------------------
// Kernel B: persistent GRU + MLP. 192 threads = one W_hh row each (in regs).
// Grid-stride over timesteps; per step: gh = W_hh @ h (64 FMA/thread), then
// gate combine by threads<64; finally MLP(H->H->4).
// ---------------------------------------------------------------------------
__global__ void __launch_bounds__(192) gru_kernel(
    const float* __restrict__ W_hh,
    const float* __restrict__ b_hh,
    const float* __restrict__ W1,
    const float* __restrict__ b1,
    const float* __restrict__ W2,
    const float* __restrict__ b2,
    float* __restrict__ out,
    int n)
{
    __shared__ __align__(16) float h_sh[HID];
    __shared__ float gh_sh[G3];
    __shared__ __align__(16) float hid_sh[HID];

    const int j = threadIdx.x;   // 0..191, gate row index

    // my W_hh row -> registers (once per block)
    float w[HID];
    #pragma unroll
    for (int k = 0; k < HID; k += 4) {
        float4 v = *reinterpret_cast<const float4*>(&W_hh[j * HID + k]);
        w[k] = v.x; w[k + 1] = v.y; w[k + 2] = v.z; w[k + 3] = v.w;
    }
    const float bhh = b_hh[j];
    const float b1j = (j < HID) ? b1[j] : 0.f;

    for (int t = blockIdx.x; t < n; t += gridDim.x) {
        const int start = g_start[t];
        if (j < HID) h_sh[j] = 0.f;
        __syncthreads();

        for (int g = start; g <= t; ++g) {
            // prefetch my input-gate values (L2-resident, overlaps the dot)
            float gir = 0.f, giz = 0.f, gin = 0.f;
            if (j < HID) {
                const float* gi = &g_GI[g * G3 + j];
                gir = __ldg(gi);
                giz = __ldg(gi + HID);
                gin = __ldg(gi + 2 * HID);
            }

            // gh[j] = b_hh[j] + dot(W_hh[j], h)   (4-way split accumulators)
            const float4* h4 = reinterpret_cast<const float4*>(h_sh);
            float a0 = bhh, a1 = 0.f, a2 = 0.f, a3 = 0.f;
            #pragma unroll
            for (int k = 0; k < 16; k += 4) {
                float4 x0 = h4[k + 0], x1 = h4[k + 1], x2 = h4[k + 2], x3 = h4[k + 3];
                a0 = fmaf(w[4*k + 0],  x0.x, a0);
                a0 = fmaf(w[4*k + 1],  x0.y, a0);
                a0 = fmaf(w[4*k + 2],  x0.z, a0);
                a0 = fmaf(w[4*k + 3],  x0.w, a0);
                a1 = fmaf(w[4*k + 4],  x1.x, a1);
                a1 = fmaf(w[4*k + 5],  x1.y, a1);
                a1 = fmaf(w[4*k + 6],  x1.z, a1);
                a1 = fmaf(w[4*k + 7],  x1.w, a1);
                a2 = fmaf(w[4*k + 8],  x2.x, a2);
                a2 = fmaf(w[4*k + 9],  x2.y, a2);
                a2 = fmaf(w[4*k + 10], x2.z, a2);
                a2 = fmaf(w[4*k + 11], x2.w, a2);
                a3 = fmaf(w[4*k + 12], x3.x, a3);
                a3 = fmaf(w[4*k + 13], x3.y, a3);
                a3 = fmaf(w[4*k + 14], x3.z, a3);
                a3 = fmaf(w[4*k + 15], x3.w, a3);
            }
            gh_sh[j] = (a0 + a1) + (a2 + a3);
            __syncthreads();

            if (j < HID) {
                float r  = sigmoidf_(gir + gh_sh[j]);
                float z  = sigmoidf_(giz + gh_sh[HID + j]);
                float nn = tanhf_(gin + r * gh_sh[2 * HID + j]);
                float hp = h_sh[j];
                h_sh[j] = (1.0f - z) * nn + z * hp;
            }
            __syncthreads();
        }

        // MLP: hid = relu(W1 @ h + b1)
        if (j < HID) {
            const float4* h4  = reinterpret_cast<const float4*>(h_sh);
            const float4* w1r = reinterpret_cast<const float4*>(&W1[j * HID]);
            float a0 = b1j, a1 = 0.f, a2 = 0.f, a3 = 0.f;
            #pragma unroll
            for (int k = 0; k < 16; k += 4) {
                float4 c0 = __ldg(&w1r[k + 0]); float4 x0 = h4[k + 0];
                float4 c1 = __ldg(&w1r[k + 1]); float4 x1 = h4[k + 1];
                float4 c2 = __ldg(&w1r[k + 2]); float4 x2 = h4[k + 2];
                float4 c3 = __ldg(&w1r[k + 3]); float4 x3 = h4[k + 3];
                a0 = fmaf(c0.x, x0.x, a0); a0 = fmaf(c0.y, x0.y, a0);
                a0 = fmaf(c0.z, x0.z, a0); a0 = fmaf(c0.w, x0.w, a0);
                a1 = fmaf(c1.x, x1.x, a1); a1 = fmaf(c1.y, x1.y, a1);
                a1 = fmaf(c1.z, x1.z, a1); a1 = fmaf(c1.w, x1.w, a1);
                a2 = fmaf(c2.x, x2.x, a2); a2 = fmaf(c2.y, x2.y, a2);
                a2 = fmaf(c2.z, x2.z, a2); a2 = fmaf(c2.w, x2.w, a2);
                a3 = fmaf(c3.x, x3.x, a3); a3 = fmaf(c3.y, x3.y, a3);
                a3 = fmaf(c3.z, x3.z, a3); a3 = fmaf(c3.w, x3.w, a3);
            }
            float hv = (a0 + a1) + (a2 + a3);
            hid_sh[j] = hv > 0.f ? hv : 0.f;
        }
        __syncthreads();

        // out = W2 @ hid + b2   (4 rows)
        if (j < DIM_C) {
            const float4* w2r = reinterpret_cast<const float4*>(&W2[j * HID]);
            const float4* x4  = reinterpret_cast<const float4*>(hid_sh);
            float a0 = b2[j], a1 = 0.f, a2 = 0.f, a3 = 0.f;
            #pragma unroll
            for (int k = 0; k < 16; k += 4) {
                float4 c0 = __ldg(&w2r[k + 0]); float4 x0 = x4[k + 0];
                float4 c1 = __ldg(&w2r[k + 1]); float4 x1 = x4[k + 1];
                float4 c2 = __ldg(&w2r[k + 2]); float4 x2 = x4[k + 2];
                float4 c3 = __ldg(&w2r[k + 3]); float4 x3 = x4[k + 3];
                a0 = fmaf(c0.x, x0.x, a0); a0 = fmaf(c0.y, x0.y, a0);
                a0 = fmaf(c0.z, x0.z, a0); a0 = fmaf(c0.w, x0.w, a0);
                a1 = fmaf(c1.x, x1.x, a1); a1 = fmaf(c1.y, x1.y, a1);
                a1 = fmaf(c1.z, x1.z, a1); a1 = fmaf(c1.w, x1.w, a1);
                a2 = fmaf(c2.x, x2.x, a2); a2 = fmaf(c2.y, x2.y, a2);
                a2 = fmaf(c2.z, x2.z, a2); a2 = fmaf(c2.w, x2.w, a2);
                a3 = fmaf(c3.x, x3.x, a3); a3 = fmaf(c3.y, x3.y, a3);
                a3 = fmaf(c3.z, x3.z, a3); a3 = fmaf(c3.w, x3.w, a3);
            }
            out[t * DIM_C + j] = (a0 + a1) + (a2 + a3);
        }
        __syncthreads();   // protect h_sh/hid_sh before next timestep
    }
}

extern "C" void kernel_launch(void* const* d_in, const int* in_sizes, int n_in,
                              void* d_out, int out_size)
{
    const float* emb   = (const float*)d_in[0];
    const float* W_ih  = (const float*)d_in[1];
    const float* W_hh  = (const float*)d_in[2];
    const float* b_ih  = (const float*)d_in[3];
    const float* b_hh  = (const float*)d_in[4];
    const float* W1    = (const float*)d_in[5];
    const float* b1    = (const float*)d_in[6];
    const float* W2    = (const float*)d_in[7];
    const float* b2    = (const float*)d_in[8];
    const int*   dones = (const int*)d_in[9];
    float* out = (float*)d_out;

    int n = in_sizes[0] / D_IN;
    if (n > MAXN) n = MAXN;

    precompute_kernel<<<(n + 63) / 64, 192>>>(emb, W_ih, b_ih, dones, n);
    gru_kernel<<<888, 192>>>(W_hh, b_hh, W1, b1, W2, b2, out, n);
}

// round 7
// speedup vs baseline: 3.4680x; 3.4680x over previous
#include <cuda_runtime.h>
#include <cuda_bf16.h>
#include <cstdint>

#define LEN_HIS 20
#define D_IN    36
#define HID     64
#define G3      192
#define DIM_C   4
#define MAXN    32768
#define M_TILE  64      // timesteps per block; 4 warps x 16 rows

// ---------------- scratch ----------------
__device__ float g_GI[MAXN * G3];   // b_ih + b_hh(r,z) folded in
__device__ int   g_start[MAXN];

// ---------------- smem layout (bytes) ----------------
#define OFF_WHH_HI 0
#define OFF_WHH_LO 24576
#define OFF_W1_HI  49152
#define OFF_W1_LO  57344
#define SMEM_SZ    65536

#define SWZ(o) ((o) ^ (((o) >> 3) & 0x70))

// ---------------- helpers ----------------
__device__ __forceinline__ float sigmoidf_(float x) {
    return __fdividef(1.0f, 1.0f + __expf(-x));
}
__device__ __forceinline__ float tanhf_(float x) {
    return __fdividef(2.0f, 1.0f + __expf(-2.0f * x)) - 1.0f;
}
__device__ __forceinline__ uint32_t smem_u32(const void* p) {
    uint32_t a;
    asm("{ .reg .u64 t; cvta.to.shared.u64 t, %1; cvt.u32.u64 %0, t; }" : "=r"(a) : "l"(p));
    return a;
}
__device__ __forceinline__ void ldsm4(uint32_t* r, uint32_t addr) {
    asm volatile("ldmatrix.sync.aligned.m8n8.x4.shared.b16 {%0,%1,%2,%3}, [%4];"
        : "=r"(r[0]), "=r"(r[1]), "=r"(r[2]), "=r"(r[3]) : "r"(addr));
}
__device__ __forceinline__ void mma16816(float* d, const uint32_t* a, uint32_t b0, uint32_t b1) {
    asm volatile("mma.sync.aligned.m16n8k16.row.col.f32.bf16.bf16.f32 "
        "{%0,%1,%2,%3}, {%4,%5,%6,%7}, {%8,%9}, {%0,%1,%2,%3};"
        : "+f"(d[0]), "+f"(d[1]), "+f"(d[2]), "+f"(d[3])
        : "r"(a[0]), "r"(a[1]), "r"(a[2]), "r"(a[3]), "r"(b0), "r"(b1));
}
// bf16 split with truncation (x = hi + r exactly; lo = bf16(r) -> ~2^-17 total)
__device__ __forceinline__ void split_pack(float x, float y, uint32_t& hi, uint32_t& lo) {
    uint32_t fx = __float_as_uint(x), fy = __float_as_uint(y);
    hi = (fy & 0xffff0000u) | (fx >> 16);
    float lx = x - __uint_as_float(fx & 0xffff0000u);
    float ly = y - __uint_as_float(fy & 0xffff0000u);
    uint32_t flx = __float_as_uint(lx), fly = __float_as_uint(ly);
    lo = (fly & 0xffff0000u) | (flx >> 16);
}
__device__ __forceinline__ float unpk_lo(uint32_t u) { return __uint_as_float(u << 16); }
__device__ __forceinline__ float unpk_hi(uint32_t u) { return __uint_as_float(u & 0xffff0000u); }

// ---------------------------------------------------------------------------
// Kernel A: GI[t][j] = b_ih[j] + (j<128 ? b_hh[j] : 0) + emb[t] . W_ih[j]
//           plus window starts.
// ---------------------------------------------------------------------------
__global__ void __launch_bounds__(192) precompute_kernel(
    const float* __restrict__ emb, const float* __restrict__ W_ih,
    const float* __restrict__ b_ih, const float* __restrict__ b_hh,
    const int* __restrict__ dones, int n)
{
    __shared__ float sW[D_IN * G3];
    __shared__ float sX[64 * D_IN];
    const int tid = threadIdx.x;
    const int t0  = blockIdx.x * 64;

    for (int idx = tid; idx < G3 * D_IN; idx += 192) {
        int j = idx / D_IN, k = idx % D_IN;
        sW[k * G3 + j] = W_ih[idx];
    }
    const int nt = min(64, n - t0);
    for (int idx = tid; idx < nt * D_IN; idx += 192)
        sX[idx] = emb[t0 * D_IN + idx];
    __syncthreads();

    const float bj = b_ih[tid] + (tid < 128 ? b_hh[tid] : 0.f);
    for (int tt = 0; tt < nt; ++tt) {
        float a0 = bj, a1 = 0.f, a2 = 0.f, a3 = 0.f;
        const float* x = &sX[tt * D_IN];
        #pragma unroll
        for (int k = 0; k < 36; k += 4) {
            a0 = fmaf(sW[(k + 0) * G3 + tid], x[k + 0], a0);
            a1 = fmaf(sW[(k + 1) * G3 + tid], x[k + 1], a1);
            a2 = fmaf(sW[(k + 2) * G3 + tid], x[k + 2], a2);
            a3 = fmaf(sW[(k + 3) * G3 + tid], x[k + 3], a3);
        }
        g_GI[(t0 + tt) * G3 + tid] = (a0 + a1) + (a2 + a3);
    }

    if (tid < 64) {
        int t = t0 + tid;
        if (t < n) {
            int s = t - (LEN_HIS - 1);
            if (s < 0) s = 0;
            int st = s;
            for (int k = s; k < t; ++k)
                if (dones[k] != 0) st = k + 1;
            g_start[t] = st;
        }
    }
}

// ---------------------------------------------------------------------------
// Kernel B: warp-MMA batched GRU. Each warp owns 16 timesteps; hidden state
// lives in A-fragment registers (bf16 hi/lo). GH = H @ Whh^T via 3-split
// m16n8k16 MMAs. New h values go into a DOUBLE BUFFER (n_hi/n_lo) so every
// MMA of a step sees only the OLD h; copied into a_hi/a_lo once per step.
// No __syncthreads in the main loop.
// ---------------------------------------------------------------------------
__global__ void __launch_bounds__(128) gru_mma_kernel(
    const float* __restrict__ Whh, const float* __restrict__ bhh,
    const float* __restrict__ W1,  const float* __restrict__ b1,
    const float* __restrict__ W2,  const float* __restrict__ b2,
    float* __restrict__ out, int n)
{
    extern __shared__ __align__(1024) char smem[];
    const int tid = threadIdx.x;
    const int l   = tid & 31;
    const int w   = tid >> 5;

    // stage Whh (192x64) and W1 (64x64) hi/lo, SW128-swizzled 128B rows
    for (int i = tid; i < G3 * HID; i += 128) {
        float v = Whh[i];
        int row = i >> 6, col = i & 63;
        uint32_t off = SWZ((uint32_t)(row * 128 + col * 2));
        __nv_bfloat16 hi = __float2bfloat16(v);
        __nv_bfloat16 lo = __float2bfloat16(v - __bfloat162float(hi));
        *reinterpret_cast<__nv_bfloat16*>(smem + OFF_WHH_HI + off) = hi;
        *reinterpret_cast<__nv_bfloat16*>(smem + OFF_WHH_LO + off) = lo;
    }
    for (int i = tid; i < HID * HID; i += 128) {
        float v = W1[i];
        int row = i >> 6, col = i & 63;
        uint32_t off = SWZ((uint32_t)(row * 128 + col * 2));
        __nv_bfloat16 hi = __float2bfloat16(v);
        __nv_bfloat16 lo = __float2bfloat16(v - __bfloat162float(hi));
        *reinterpret_cast<__nv_bfloat16*>(smem + OFF_W1_HI + off) = hi;
        *reinterpret_cast<__nv_bfloat16*>(smem + OFF_W1_LO + off) = lo;
    }
    __syncthreads();

    const uint32_t sb = smem_u32(smem);
    const int c2 = (l & 3) * 2;                   // col pair within 8-wide tile
    const int t0 = blockIdx.x * M_TILE + w * 16 + (l >> 2);
    const int t1 = t0 + 8;
    const int start0 = (t0 < n) ? g_start[t0] : 0;
    const int start1 = (t1 < n) ? g_start[t1] : 0;

    // first step at which each row's window opens (h==0 before that -> skip)
    int first0 = (t0 < n) ? max(0, start0 - t0 + (LEN_HIS - 1)) : LEN_HIS;
    int first1 = (t1 < n) ? max(0, start1 - t1 + (LEN_HIS - 1)) : LEN_HIS;
    const int warp_first = __reduce_min_sync(0xffffffffu, min(first0, first1));

    // b_hh for the n-gate at my column pairs
    float2 bhn[8];
    #pragma unroll
    for (int g = 0; g < 8; ++g)
        bhn[g] = *reinterpret_cast<const float2*>(&bhh[2 * HID + 8 * g + c2]);

    // ldmatrix address pieces for B tiles
    const int bn_row = (l & 7);
    const int bn_k   = (l >> 3) * 8;

    // hidden-state A fragments: [k-tile 0..3][a0..a3], bf16x2 packed
    uint32_t a_hi[4][4], a_lo[4][4];
    #pragma unroll
    for (int i = 0; i < 4; ++i)
        #pragma unroll
        for (int jx = 0; jx < 4; ++jx) { a_hi[i][jx] = 0u; a_lo[i][jx] = 0u; }

    for (int step = warp_first; step < LEN_HIS; ++step) {
        const int g0 = t0 - (LEN_HIS - 1) + step;
        const int g1 = t1 - (LEN_HIS - 1) + step;
        const bool v0 = (t0 < n) && (g0 >= start0);
        const bool v1 = (t1 < n) && (g1 >= start1);
        const float* gp0 = &g_GI[(v0 ? g0 : 0) * G3 + c2];
        const float* gp1 = &g_GI[(v1 ? g1 : 0) * G3 + c2];

        uint32_t n_hi[4][4], n_lo[4][4];   // NEW h (double buffer)

        #pragma unroll
        for (int ntg = 0; ntg < 8; ++ntg) {
            float acc[3][4];
            #pragma unroll
            for (int gi = 0; gi < 3; ++gi)
                #pragma unroll
                for (int ci = 0; ci < 4; ++ci) acc[gi][ci] = 0.f;

            #pragma unroll
            for (int gate = 0; gate < 3; ++gate) {
                const int nt = gate * 8 + ntg;
                #pragma unroll
                for (int kh = 0; kh < 2; ++kh) {
                    uint32_t bh[4], bl[4];
                    uint32_t boff = SWZ((uint32_t)((nt * 8 + bn_row) * 128 + (kh * 32 + bn_k) * 2));
                    ldsm4(bh, sb + OFF_WHH_HI + boff);
                    ldsm4(bl, sb + OFF_WHH_LO + boff);
                    #pragma unroll
                    for (int k2 = 0; k2 < 2; ++k2) {
                        const int kt = kh * 2 + k2;
                        mma16816(acc[gate], a_hi[kt], bh[k2 * 2], bh[k2 * 2 + 1]); // hi*hi
                        mma16816(acc[gate], a_lo[kt], bh[k2 * 2], bh[k2 * 2 + 1]); // lo*hi
                        mma16816(acc[gate], a_hi[kt], bl[k2 * 2], bl[k2 * 2 + 1]); // hi*lo
                    }
                }
            }

            // gate update into the double buffer (reads only OLD fragments)
            const int kt = ntg >> 1;
            const int sl = (ntg & 1) * 2;
            #pragma unroll
            for (int rh = 0; rh < 2; ++rh) {
                const bool vv = rh ? v1 : v0;
                const float* gp = rh ? gp1 : gp0;
                const int slot = sl + rh;
                float hx = unpk_lo(a_hi[kt][slot]) + unpk_lo(a_lo[kt][slot]);
                float hy = unpk_hi(a_hi[kt][slot]) + unpk_hi(a_lo[kt][slot]);
                if (vv) {
                    float2 gr = *reinterpret_cast<const float2*>(gp + 8 * ntg);
                    float2 gz = *reinterpret_cast<const float2*>(gp + HID + 8 * ntg);
                    float2 gn = *reinterpret_cast<const float2*>(gp + 2 * HID + 8 * ntg);
                    const float ar0 = acc[0][rh * 2], ar1 = acc[0][rh * 2 + 1];
                    const float az0 = acc[1][rh * 2], az1 = acc[1][rh * 2 + 1];
                    const float an0 = acc[2][rh * 2], an1 = acc[2][rh * 2 + 1];
                    float r0 = sigmoidf_(gr.x + ar0);
                    float r1 = sigmoidf_(gr.y + ar1);
                    float z0 = sigmoidf_(gz.x + az0);
                    float z1 = sigmoidf_(gz.y + az1);
                    float n0 = tanhf_(gn.x + r0 * (an0 + bhn[ntg].x));
                    float n1 = tanhf_(gn.y + r1 * (an1 + bhn[ntg].y));
                    hx = n0 + z0 * (hx - n0);
                    hy = n1 + z1 * (hy - n1);
                }
                split_pack(hx, hy, n_hi[kt][slot], n_lo[kt][slot]);
            }
        }

        // commit new h for the next step
        #pragma unroll
        for (int i = 0; i < 4; ++i)
            #pragma unroll
            for (int jx = 0; jx < 4; ++jx) {
                a_hi[i][jx] = n_hi[i][jx];
                a_lo[i][jx] = n_lo[i][jx];
            }
    }

    // ---- MLP layer 1 via MMA: hid = relu(h @ W1^T + b1) ----
    float hidv[8][4];
    #pragma unroll
    for (int ntg = 0; ntg < 8; ++ntg) {
        float acc[4] = {0.f, 0.f, 0.f, 0.f};
        #pragma unroll
        for (int kh = 0; kh < 2; ++kh) {
            uint32_t bh[4], bl[4];
            uint32_t boff = SWZ((uint32_t)((ntg * 8 + bn_row) * 128 + (kh * 32 + bn_k) * 2));
            ldsm4(bh, sb + OFF_W1_HI + boff);
            ldsm4(bl, sb + OFF_W1_LO + boff);
            #pragma unroll
            for (int k2 = 0; k2 < 2; ++k2) {
                const int kt = kh * 2 + k2;
                mma16816(acc, a_hi[kt], bh[k2 * 2], bh[k2 * 2 + 1]);
                mma16816(acc, a_lo[kt], bh[k2 * 2], bh[k2 * 2 + 1]);
                mma16816(acc, a_hi[kt], bl[k2 * 2], bl[k2 * 2 + 1]);
            }
        }
        float2 b1v = *reinterpret_cast<const float2*>(&b1[8 * ntg + c2]);
        float h0 = acc[0] + b1v.x, h1 = acc[1] + b1v.y;
        float h2 = acc[2] + b1v.x, h3 = acc[3] + b1v.y;
        hidv[ntg][0] = h0 > 0.f ? h0 : 0.f;
        hidv[ntg][1] = h1 > 0.f ? h1 : 0.f;
        hidv[ntg][2] = h2 > 0.f ? h2 : 0.f;
        hidv[ntg][3] = h3 > 0.f ? h3 : 0.f;
    }

    // ---- out = W2 @ hid + b2 (scalar partials + quad butterfly reduce) ----
    float po0[4] = {0.f, 0.f, 0.f, 0.f};
    float po1[4] = {0.f, 0.f, 0.f, 0.f};
    #pragma unroll
    for (int ntg = 0; ntg < 8; ++ntg) {
        #pragma unroll
        for (int c = 0; c < 4; ++c) {
            float2 w2v = *reinterpret_cast<const float2*>(&W2[c * HID + 8 * ntg + c2]);
            po0[c] = fmaf(w2v.x, hidv[ntg][0], fmaf(w2v.y, hidv[ntg][1], po0[c]));
            po1[c] = fmaf(w2v.x, hidv[ntg][2], fmaf(w2v.y, hidv[ntg][3], po1[c]));
        }
    }
    #pragma unroll
    for (int c = 0; c < 4; ++c) {
        po0[c] += __shfl_xor_sync(0xffffffffu, po0[c], 1);
        po0[c] += __shfl_xor_sync(0xffffffffu, po0[c], 2);
        po1[c] += __shfl_xor_sync(0xffffffffu, po1[c], 1);
        po1[c] += __shfl_xor_sync(0xffffffffu, po1[c], 2);
    }
    const int c = l & 3;
    if (t0 < n) out[t0 * DIM_C + c] = po0[c] + b2[c];
    if (t1 < n) out[t1 * DIM_C + c] = po1[c] + b2[c];
}

// ---------------------------------------------------------------------------
extern "C" void kernel_launch(void* const* d_in, const int* in_sizes, int n_in,
                              void* d_out, int out_size)
{
    const float* emb   = (const float*)d_in[0];
    const float* W_ih  = (const float*)d_in[1];
    const float* W_hh  = (const float*)d_in[2];
    const float* b_ih  = (const float*)d_in[3];
    const float* b_hh  = (const float*)d_in[4];
    const float* W1    = (const float*)d_in[5];
    const float* b1    = (const float*)d_in[6];
    const float* W2    = (const float*)d_in[7];
    const float* b2    = (const float*)d_in[8];
    const int*   dones = (const int*)d_in[9];
    float* out = (float*)d_out;

    int n = in_sizes[0] / D_IN;
    if (n > MAXN) n = MAXN;

    cudaFuncSetAttribute(gru_mma_kernel, cudaFuncAttributeMaxDynamicSharedMemorySize, SMEM_SZ);

    precompute_kernel<<<(n + 63) / 64, 192>>>(emb, W_ih, b_ih, b_hh, dones, n);
    gru_mma_kernel<<<(n + M_TILE - 1) / M_TILE, 128, SMEM_SZ>>>(W_hh, b_hh, W1, b1, W2, b2, out, n);
}